// round 4
// baseline (speedup 1.0000x reference)
#include <cuda_runtime.h>
#include <cuda_fp16.h>
#include <stdint.h>

#define DI __device__ __forceinline__
#define N_NODES 8192
#define F_IN    512
#define F_OUT   256
#define K1      1536

__device__ __align__(16) __half g_xh[(size_t)N_NODES * K1];
__device__ __align__(16) __half g_wt[(size_t)F_OUT * K1];
__device__ __align__(16) float  g_h [(size_t)N_NODES * F_OUT];
__device__ __align__(16) __half g_wht[(size_t)F_OUT * N_NODES];
__device__ __align__(16) float  g_b[N_NODES];
__device__ __align__(16) float  g_w[N_NODES];
__device__ float g_u[F_IN];
__device__ float g_c;

extern __shared__ __align__(16) char dynsm[];

DI uint32_t sm_u32(const void* p){ return (uint32_t)__cvta_generic_to_shared(p); }
DI void cp16(uint32_t d, const void* s){ asm volatile("cp.async.cg.shared.global [%0],[%1],16;\n"::"r"(d),"l"(s)); }
DI void cpcommit(){ asm volatile("cp.async.commit_group;\n":::"memory"); }
template<int N> DI void cpwaitg(){ asm volatile("cp.async.wait_group %0;\n"::"n"(N):"memory"); }

DI void mma16816(float* c, const uint32_t* a, uint32_t b0, uint32_t b1){
  asm volatile("mma.sync.aligned.m16n8k16.row.col.f32.f16.f16.f32 "
    "{%0,%1,%2,%3},{%4,%5,%6,%7},{%8,%9},{%0,%1,%2,%3};\n"
    : "+f"(c[0]),"+f"(c[1]),"+f"(c[2]),"+f"(c[3])
    : "r"(a[0]),"r"(a[1]),"r"(a[2]),"r"(a[3]),"r"(b0),"r"(b1));
}
DI void ldsm4(uint32_t* r, uint32_t a){
  asm volatile("ldmatrix.sync.aligned.m8n8.x4.shared.b16 {%0,%1,%2,%3},[%4];"
    : "=r"(r[0]),"=r"(r[1]),"=r"(r[2]),"=r"(r[3]) : "r"(a));
}

// Block tile 64(m) x 256(n) x 64(k); 8 warps = 2(m) x 4(n); warp tile 32x64.
// Shared tiles: row = 64 halves (128B), 8x16B chunks, chunk XOR (row&7) swizzle.
// All operand loads via ldmatrix.x4 (fragment layouts match mma.m16n8k16 exactly).
DI void mma_tile(uint32_t Asb, uint32_t Bsb, float (&acc)[2][8][4],
                 int wm, int wn, int lane){
  const int la7 = lane & 7;
  const int rowa0 = wm*32 + (lane & 8) + la7;          // + mi*16
  const uint32_t ca0 = (uint32_t)(lane >> 4);          // k-chunk parity for A
  const int rowb0 = wn*64 + ((lane >> 4) << 3) + la7;  // + nj*16
  const uint32_t cb0 = (uint32_t)((lane >> 3) & 1);    // k-chunk parity for B
#pragma unroll
  for (int kk4 = 0; kk4 < 4; kk4++){
    uint32_t a[2][4];
#pragma unroll
    for (int mi = 0; mi < 2; mi++){
      int row = rowa0 + mi*16;
      uint32_t ad = Asb + row*128 + (((((uint32_t)kk4<<1)|ca0) ^ (uint32_t)(row&7)) << 4);
      ldsm4(a[mi], ad);
    }
#pragma unroll
    for (int nj = 0; nj < 4; nj++){
      int row = rowb0 + nj*16;
      uint32_t bd = Bsb + row*128 + (((((uint32_t)kk4<<1)|cb0) ^ (uint32_t)(row&7)) << 4);
      uint32_t b[4]; ldsm4(b, bd);
      mma16816(acc[0][2*nj],   a[0], b[0], b[1]);
      mma16816(acc[1][2*nj],   a[1], b[0], b[1]);
      mma16816(acc[0][2*nj+1], a[0], b[2], b[3]);
      mma16816(acc[1][2*nj+1], a[1], b[2], b[3]);
    }
  }
}

// ---------------- pre-kernels (merged to control launch order) ----------------
// blocks [0,16384): split x -> [hi|hi|lo]; blocks [16384,16896): W^T -> [hi|lo|hi]
__global__ void k_convxw(const float* __restrict__ x, const float* __restrict__ wgt){
  if (blockIdx.x < 16384){
    int idx = blockIdx.x*256 + threadIdx.x;
    int j = idx >> 9, k = idx & 511;
    float v = x[idx];
    __half hi = __float2half_rn(v);
    __half lo = __float2half_rn(v - __half2float(hi));
    size_t base = (size_t)j*K1 + k;
    g_xh[base] = hi; g_xh[base+512] = hi; g_xh[base+1024] = lo;
  } else {
    int idx = (blockIdx.x-16384)*256 + threadIdx.x;
    int k = idx >> 8, f = idx & 255;
    float v = wgt[idx];
    __half hi = __float2half_rn(v);
    __half lo = __float2half_rn(v - __half2float(hi));
    size_t base = (size_t)f*K1 + k;
    g_wt[base] = hi; g_wt[base+512] = lo; g_wt[base+1024] = hi;
  }
}
// u = W @ phi_dst (warp per k-row); last warp group: c = bias . phi_dst
__global__ void k_ucc(const float* __restrict__ wgt, const float* __restrict__ bias,
                      const float* __restrict__ phi){
  int gw = (blockIdx.x*256 + threadIdx.x) >> 5;
  int lane = threadIdx.x & 31;
  if (gw < F_IN){
    float s = 0.f;
#pragma unroll
    for (int i=0;i<8;i++){ int f=i*32+lane; s += wgt[gw*256+f]*phi[256+f]; }
    for (int o=16;o;o>>=1) s += __shfl_down_sync(0xFFFFFFFFu, s, o);
    if (!lane) g_u[gw] = s;
  } else if (gw == F_IN){
    float s = 0.f;
#pragma unroll
    for (int i=0;i<8;i++){ int f=i*32+lane; s += bias[f]*phi[256+f]; }
    for (int o=16;o;o>>=1) s += __shfl_down_sync(0xFFFFFFFFu, s, o);
    if (!lane) g_c = s;
  }
}
// b = x @ u + c  (fp32 exact: softmax weights are the error-sensitive path)
__global__ void k_bvec(const float* __restrict__ x){
  __shared__ float su[F_IN];
  for (int i=threadIdx.x; i<F_IN; i+=256) su[i] = g_u[i];
  __syncthreads();
  int row = blockIdx.x*8 + (threadIdx.x >> 5);
  int lane = threadIdx.x & 31;
  const float* xr = x + (size_t)row*F_IN;
  float s = 0.f;
#pragma unroll
  for (int i=0;i<16;i++){ int k=i*32+lane; s += xr[k]*su[k]; }
  for (int o=16;o;o>>=1) s += __shfl_down_sync(0xFFFFFFFFu, s, o);
  if (!lane) g_b[row] = s + g_c;
}
// global max + w = exp(b - max) in one block
__global__ void k_maxw(){
  __shared__ float s[1024];
  int t = threadIdx.x;
  float m = -3.4e38f;
  for (int i=t; i<N_NODES; i+=1024) m = fmaxf(m, g_b[i]);
  s[t] = m; __syncthreads();
  for (int o=512;o;o>>=1){ if (t<o) s[t]=fmaxf(s[t],s[t+o]); __syncthreads(); }
  float gm = s[0];
  for (int i=t; i<N_NODES; i+=1024) g_w[i] = expf(g_b[i] - gm);
}
// wht[f][j] = fp16(w[j]*h[j][f]) via smem transpose
__global__ void k_wht(){
  __shared__ float s[32][33];
  int j0 = blockIdx.x*32, f0 = blockIdx.y*32;
  int tx = threadIdx.x & 31, ty = threadIdx.x >> 5;
#pragma unroll
  for (int q=0;q<4;q++) s[ty+8*q][tx] = g_h[(size_t)(j0+ty+8*q)*F_OUT + f0+tx];
  __syncthreads();
  float wj = g_w[j0+tx];
#pragma unroll
  for (int q=0;q<4;q++)
    g_wht[(size_t)(f0+ty+8*q)*N_NODES + j0+tx] = __float2half_rn(wj * s[tx][ty+8*q]);
}

// ---------------- GEMM1: h = xh @ wt^T + bias  (M=8192,N=256,K=1536) ----------------
__global__ void __launch_bounds__(256) k_gemm1(const float* __restrict__ bias){
  __half* As = (__half*)dynsm;       // 2 * 64*64
  __half* Bs = As + 8192;            // 2 * 256*64
  int t = threadIdx.x, bm = blockIdx.x;
  int warp = t>>5, lane = t&31, wm = warp&1, wn = warp>>1, g = lane>>2, tg = lane&3;
  float acc[2][8][4] = {};
  const int KT = K1/64;
  auto cpA = [&](int buf, int kt){
#pragma unroll
    for (int i=0;i<2;i++){
      int idx = t + i*256, row = idx>>3, c8 = idx&7;
      uint32_t d = sm_u32(As + buf*4096) + row*128 + ((c8 ^ (row&7)) << 4);
      cp16(d, g_xh + (size_t)(bm*64+row)*K1 + kt*64 + c8*8);
    }
  };
  auto cpB = [&](int buf, int kt){
    uint32_t d = sm_u32(Bs + buf*16384) + (uint32_t)t*128;
    const __half* s = g_wt + (size_t)t*K1 + kt*64;
    int sw = t & 7;
#pragma unroll
    for (int i=0;i<8;i++) cp16(d + ((i^sw)<<4), s + i*8);
  };
  cpA(0,0); cpB(0,0); cpcommit();
  for (int kt=0; kt<KT; kt++){
    int cur = kt&1, nxt = cur^1;
    __syncthreads();
    if (kt+1 < KT){ cpA(nxt,kt+1); cpB(nxt,kt+1); cpcommit(); cpwaitg<1>(); }
    else cpwaitg<0>();
    __syncthreads();
    mma_tile(sm_u32(As + cur*4096), sm_u32(Bs + cur*16384), acc, wm, wn, lane);
  }
#pragma unroll
  for (int mi=0; mi<2; mi++)
#pragma unroll
    for (int ni=0; ni<8; ni++){
      int r = wm*32 + mi*16 + g, c = wn*64 + ni*8 + tg*2;
      float2 bv = *(const float2*)(bias + c);
      size_t go = (size_t)(bm*64+r)*F_OUT + c;
      *(float2*)(g_h+go)         = make_float2(acc[mi][ni][0]+bv.x, acc[mi][ni][1]+bv.y);
      *(float2*)(g_h+go+8*F_OUT) = make_float2(acc[mi][ni][2]+bv.x, acc[mi][ni][3]+bv.y);
    }
}

// ---------------- GEMM2: out = relu((MASK @ wht^T) / (MASK @ w)) ----------------
// M=8192,N=256,K=8192. A (0/1 mask) built in-register from adj ints -> fp16 smem;
// denominator accumulated in fp32 alongside. B streamed via cp.async.
__global__ void __launch_bounds__(256) k_gemm2(const int* __restrict__ adj, float* __restrict__ out){
  __half* As = (__half*)dynsm;            // 2 * 64*64   (16 KB)
  __half* Bs = As + 8192;                 // 2 * 256*64  (64 KB)
  float*  wsm = (float*)(Bs + 32768);     // 32 KB
  __shared__ float sred[64][16];
  __shared__ float sden[64];
  int t = threadIdx.x, bm = blockIdx.x;
  int warp = t>>5, lane = t&31, wm = warp&1, wn = warp>>1, g = lane>>2, tg = lane&3;
  float acc[2][8][4] = {};
  float dpart[4] = {0.f,0.f,0.f,0.f};
  for (int i=t; i<2048; i+=256) ((float4*)wsm)[i] = ((const float4*)g_w)[i];
  // prologue: B tile 0 via cp.async, A ints tile 0 via LDG
  {
    uint32_t d = sm_u32(Bs) + (uint32_t)t*128;
    const __half* s = g_wht + (size_t)t*N_NODES;
    int sw = t & 7;
#pragma unroll
    for (int i=0;i<8;i++) cp16(d + ((i^sw)<<4), s + i*8);
  }
  cpcommit();
  int4 av[4];
#pragma unroll
  for (int i=0;i<4;i++){
    int idx = t + i*256, row = idx>>4, c4 = idx&15;
    av[i] = *(const int4*)(adj + (size_t)(bm*64+row)*N_NODES + c4*4);
  }
  const int KT = N_NODES/64;
  for (int kt=0; kt<KT; kt++){
    int cur = kt&1, nxt = cur^1;
    __syncthreads();
    __half* Ad = As + cur*4096;
#pragma unroll
    for (int i=0;i<4;i++){
      int idx = t + i*256, row = idx>>4, c4 = idx&15;
      int gj = kt*64 + c4*4, gi = bm*64 + row;
      int4 a = av[i];
      int m0 = (a.x!=0) | (gi==gj  );
      int m1 = (a.y!=0) | (gi==gj+1);
      int m2 = (a.z!=0) | (gi==gj+2);
      int m3 = (a.w!=0) | (gi==gj+3);
      float4 wv = ((const float4*)wsm)[kt*16 + c4];
      dpart[i] += (m0?wv.x:0.f) + (m1?wv.y:0.f) + (m2?wv.z:0.f) + (m3?wv.w:0.f);
      uint32_t u0 = (m0 ? 0x3C00u : 0u) | (m1 ? 0x3C000000u : 0u);
      uint32_t u1 = (m2 ? 0x3C00u : 0u) | (m3 ? 0x3C000000u : 0u);
      uint32_t hidx = row*64 + (((c4>>1) ^ (row&7)) << 3) + (c4&1)*4;
      *(uint2*)(Ad + hidx) = make_uint2(u0, u1);
    }
    if (kt+1 < KT){
      uint32_t d = sm_u32(Bs + nxt*16384) + (uint32_t)t*128;
      const __half* s = g_wht + (size_t)t*N_NODES + (kt+1)*64;
      int sw = t & 7;
#pragma unroll
      for (int i=0;i<8;i++) cp16(d + ((i^sw)<<4), s + i*8);
      cpcommit();
#pragma unroll
      for (int i=0;i<4;i++){
        int idx = t + i*256, row = idx>>4, c4 = idx&15;
        av[i] = *(const int4*)(adj + (size_t)(bm*64+row)*N_NODES + (kt+1)*64 + c4*4);
      }
      cpwaitg<1>();
    } else cpwaitg<0>();
    __syncthreads();
    mma_tile(sm_u32(As + cur*4096), sm_u32(Bs + cur*16384), acc, wm, wn, lane);
  }
  // fp32 denominator reduction (16 partials per row)
  __syncthreads();
#pragma unroll
  for (int i=0;i<4;i++) sred[(t>>4) + 16*i][t&15] = dpart[i];
  __syncthreads();
  if (t < 64){
    float s = 0.f;
#pragma unroll
    for (int q=0;q<16;q++) s += sred[t][q];
    sden[t] = s;
  }
  __syncthreads();
#pragma unroll
  for (int mi=0; mi<2; mi++)
#pragma unroll
    for (int ni=0; ni<8; ni++){
      int r = wm*32 + mi*16 + g, c = wn*64 + ni*8 + tg*2;
      float i0 = 1.f/sden[r], i8 = 1.f/sden[r+8];
      size_t go = (size_t)(bm*64+r)*F_OUT + c;
      *(float2*)(out+go)         = make_float2(fmaxf(acc[mi][ni][0]*i0,0.f), fmaxf(acc[mi][ni][1]*i0,0.f));
      *(float2*)(out+go+8*F_OUT) = make_float2(fmaxf(acc[mi][ni][2]*i8,0.f), fmaxf(acc[mi][ni][3]*i8,0.f));
    }
}

extern "C" void kernel_launch(void* const* d_in, const int* in_sizes, int n_in,
                              void* d_out, int out_size){
  const int*   adj  = (const int*)d_in[0];
  const float* x    = (const float*)d_in[1];
  const float* wgt  = (const float*)d_in[2];
  const float* bias = (const float*)d_in[3];
  const float* phi  = (const float*)d_in[4];
  float* out = (float*)d_out;
  cudaFuncSetAttribute(k_gemm1, cudaFuncAttributeMaxDynamicSharedMemorySize, 81920);
  cudaFuncSetAttribute(k_gemm2, cudaFuncAttributeMaxDynamicSharedMemorySize, 114688);
  k_convxw<<<16896, 256>>>(x, wgt);          // 1
  k_ucc<<<65, 256>>>(wgt, bias, phi);        // 2
  k_bvec<<<N_NODES/8, 256>>>(x);             // 3
  k_gemm1<<<128, 256, 81920>>>(bias);        // 4  <- ncu capture slot
  k_maxw<<<1, 1024>>>();                     // 5
  k_wht<<<dim3(256,8), 256>>>();             // 6
  k_gemm2<<<128, 256, 114688>>>(adj, out);   // 7
}

// round 5
// speedup vs baseline: 1.3921x; 1.3921x over previous
#include <cuda_runtime.h>
#include <cuda_fp16.h>
#include <stdint.h>

#define DI __device__ __forceinline__
#define N_NODES 8192
#define F_IN    512
#define F_OUT   256
#define K1      1536

__device__ __align__(16) __half g_xh[(size_t)N_NODES * K1];
__device__ __align__(16) __half g_wt[(size_t)F_OUT * K1];
__device__ __align__(16) float  g_h [(size_t)N_NODES * F_OUT];
__device__ __align__(16) __half g_wht[(size_t)F_OUT * N_NODES];
__device__ __align__(16) float  g_b[N_NODES];
__device__ __align__(16) float  g_w[N_NODES];
__device__ float g_u[F_IN];
__device__ float g_c;

extern __shared__ __align__(16) char dynsm[];

DI uint32_t sm_u32(const void* p){ return (uint32_t)__cvta_generic_to_shared(p); }
DI void cp16(uint32_t d, const void* s){ asm volatile("cp.async.cg.shared.global [%0],[%1],16;\n"::"r"(d),"l"(s)); }
DI void cpcommit(){ asm volatile("cp.async.commit_group;\n":::"memory"); }
template<int N> DI void cpwaitg(){ asm volatile("cp.async.wait_group %0;\n"::"n"(N):"memory"); }

DI void mma16816(float* c, const uint32_t* a, uint32_t b0, uint32_t b1){
  asm volatile("mma.sync.aligned.m16n8k16.row.col.f32.f16.f16.f32 "
    "{%0,%1,%2,%3},{%4,%5,%6,%7},{%8,%9},{%0,%1,%2,%3};\n"
    : "+f"(c[0]),"+f"(c[1]),"+f"(c[2]),"+f"(c[3])
    : "r"(a[0]),"r"(a[1]),"r"(a[2]),"r"(a[3]),"r"(b0),"r"(b1));
}
DI void ldsm4(uint32_t* r, uint32_t a){
  asm volatile("ldmatrix.sync.aligned.m8n8.x4.shared.b16 {%0,%1,%2,%3},[%4];"
    : "=r"(r[0]),"=r"(r[1]),"=r"(r[2]),"=r"(r[3]) : "r"(a));
}

// Block tile 64(m) x 256(n) x 64(k); 16 warps = 2(m) x 8(n); warp tile 32x32.
// Shared tiles: row = 64 halves (128B) = 8 x 16B chunks, chunk XOR (row&7) swizzle.
DI void mma_tile(uint32_t Asb, uint32_t Bsb, float (&acc)[2][4][4],
                 int wm, int wn, int lane){
  const int la7 = lane & 7;
  const int rowa0 = wm*32 + (lane & 8) + la7;
  const uint32_t ca0 = (uint32_t)(lane >> 4);
  const int rowb0 = wn*32 + ((lane >> 4) << 3) + la7;
  const uint32_t cb0 = (uint32_t)((lane >> 3) & 1);
#pragma unroll
  for (int kk4 = 0; kk4 < 4; kk4++){
    uint32_t a[2][4];
#pragma unroll
    for (int mi = 0; mi < 2; mi++){
      int row = rowa0 + mi*16;
      uint32_t ad = Asb + row*128 + (((((uint32_t)kk4<<1)|ca0) ^ (uint32_t)(row&7)) << 4);
      ldsm4(a[mi], ad);
    }
#pragma unroll
    for (int nj = 0; nj < 2; nj++){
      int row = rowb0 + nj*16;
      uint32_t bd = Bsb + row*128 + (((((uint32_t)kk4<<1)|cb0) ^ (uint32_t)(row&7)) << 4);
      uint32_t b[4]; ldsm4(b, bd);
      mma16816(acc[0][2*nj],   a[0], b[0], b[1]);
      mma16816(acc[1][2*nj],   a[1], b[0], b[1]);
      mma16816(acc[0][2*nj+1], a[0], b[2], b[3]);
      mma16816(acc[1][2*nj+1], a[1], b[2], b[3]);
    }
  }
}

// ---------------- pre-kernels ----------------
__global__ void k_convxw(const float* __restrict__ x, const float* __restrict__ wgt){
  if (blockIdx.x < 16384){
    int idx = blockIdx.x*256 + threadIdx.x;
    int j = idx >> 9, k = idx & 511;
    float v = x[idx];
    __half hi = __float2half_rn(v);
    __half lo = __float2half_rn(v - __half2float(hi));
    size_t base = (size_t)j*K1 + k;
    g_xh[base] = hi; g_xh[base+512] = hi; g_xh[base+1024] = lo;
  } else {
    int idx = (blockIdx.x-16384)*256 + threadIdx.x;
    int k = idx >> 8, f = idx & 255;
    float v = wgt[idx];
    __half hi = __float2half_rn(v);
    __half lo = __float2half_rn(v - __half2float(hi));
    size_t base = (size_t)f*K1 + k;
    g_wt[base] = hi; g_wt[base+512] = lo; g_wt[base+1024] = hi;
  }
}
__global__ void k_ucc(const float* __restrict__ wgt, const float* __restrict__ bias,
                      const float* __restrict__ phi){
  int gw = (blockIdx.x*256 + threadIdx.x) >> 5;
  int lane = threadIdx.x & 31;
  if (gw < F_IN){
    float s = 0.f;
#pragma unroll
    for (int i=0;i<8;i++){ int f=i*32+lane; s += wgt[gw*256+f]*phi[256+f]; }
    for (int o=16;o;o>>=1) s += __shfl_down_sync(0xFFFFFFFFu, s, o);
    if (!lane) g_u[gw] = s;
  } else if (gw == F_IN){
    float s = 0.f;
#pragma unroll
    for (int i=0;i<8;i++){ int f=i*32+lane; s += bias[f]*phi[256+f]; }
    for (int o=16;o;o>>=1) s += __shfl_down_sync(0xFFFFFFFFu, s, o);
    if (!lane) g_c = s;
  }
}
__global__ void k_bvec(const float* __restrict__ x){
  __shared__ float su[F_IN];
  for (int i=threadIdx.x; i<F_IN; i+=256) su[i] = g_u[i];
  __syncthreads();
  int row = blockIdx.x*8 + (threadIdx.x >> 5);
  int lane = threadIdx.x & 31;
  const float* xr = x + (size_t)row*F_IN;
  float s = 0.f;
#pragma unroll
  for (int i=0;i<16;i++){ int k=i*32+lane; s += xr[k]*su[k]; }
  for (int o=16;o;o>>=1) s += __shfl_down_sync(0xFFFFFFFFu, s, o);
  if (!lane) g_b[row] = s + g_c;
}
__global__ void k_maxw(){
  __shared__ float s[1024];
  int t = threadIdx.x;
  float m = -3.4e38f;
  for (int i=t; i<N_NODES; i+=1024) m = fmaxf(m, g_b[i]);
  s[t] = m; __syncthreads();
  for (int o=512;o;o>>=1){ if (t<o) s[t]=fmaxf(s[t],s[t+o]); __syncthreads(); }
  float gm = s[0];
  for (int i=t; i<N_NODES; i+=1024) g_w[i] = expf(g_b[i] - gm);
}
__global__ void k_wht(){
  __shared__ float s[32][33];
  int j0 = blockIdx.x*32, f0 = blockIdx.y*32;
  int tx = threadIdx.x & 31, ty = threadIdx.x >> 5;
#pragma unroll
  for (int q=0;q<4;q++) s[ty+8*q][tx] = g_h[(size_t)(j0+ty+8*q)*F_OUT + f0+tx];
  __syncthreads();
  float wj = g_w[j0+tx];
#pragma unroll
  for (int q=0;q<4;q++)
    g_wht[(size_t)(f0+ty+8*q)*N_NODES + j0+tx] = __float2half_rn(wj * s[tx][ty+8*q]);
}

// ---------------- GEMM1: h = xh @ wt^T + bias (M=8192,N=256,K=1536) ----------------
// 512 threads, 3-stage single-sync pipeline. As stage 8KB, Bs stage 32KB.
__global__ void __launch_bounds__(512) k_gemm1(const float* __restrict__ bias){
  char* As = dynsm;                 // 3 * 8192 B
  char* Bs = dynsm + 24576;         // 3 * 32768 B
  const int t = threadIdx.x, bm = blockIdx.x;
  const int warp = t>>5, lane = t&31, wm = warp&1, wn = warp>>1, g = lane>>2, tg = lane&3;
  float acc[2][4][4] = {};
  const int KT = K1/64;
  // A: 64 rows x 8 chunks = 512 slots (1/thread); B: 256 rows x 8 chunks (4/thread)
  const int ar = t>>3, ac = t&7;
  const int br = t>>1, bc0 = (t&1)*4;
  const uint32_t adst = sm_u32(As) + ar*128 + ((ac ^ (ar&7)) << 4);
  const __half* asrc = g_xh + (size_t)(bm*64+ar)*K1 + ac*8;
  const uint32_t bdst = sm_u32(Bs) + br*128;
  const __half* bsrc = g_wt + (size_t)br*K1 + bc0*8;
  auto fill = [&](int s, int kt){
    cp16(adst + s*8192, asrc + kt*64);
#pragma unroll
    for (int i=0;i<4;i++)
      cp16(bdst + s*32768 + (((bc0+i) ^ (br&7)) << 4), bsrc + kt*64 + i*8);
  };
  fill(0,0); cpcommit();
  fill(1,1); cpcommit();
  for (int kt=0; kt<KT; kt++){
    cpwaitg<1>();
    __syncthreads();
    if (kt+2 < KT) fill((kt+2)%3, kt+2);
    cpcommit();
    int s = kt%3;
    mma_tile(sm_u32(As) + s*8192, sm_u32(Bs) + s*32768, acc, wm, wn, lane);
  }
#pragma unroll
  for (int mi=0; mi<2; mi++)
#pragma unroll
    for (int ni=0; ni<4; ni++){
      int r = wm*32 + mi*16 + g, c = wn*32 + ni*8 + tg*2;
      float2 bv = *(const float2*)(bias + c);
      size_t go = (size_t)(bm*64+r)*F_OUT + c;
      *(float2*)(g_h+go)         = make_float2(acc[mi][ni][0]+bv.x, acc[mi][ni][1]+bv.y);
      *(float2*)(g_h+go+8*F_OUT) = make_float2(acc[mi][ni][2]+bv.x, acc[mi][ni][3]+bv.y);
    }
}

// ---------------- GEMM2: out = relu((MASK @ wht^T) / (MASK @ w)) ----------------
// M=8192,N=256,K=8192; mask built in-register from adj, denominator fused.
__global__ void __launch_bounds__(512) k_gemm2(const int* __restrict__ adj, float* __restrict__ out){
  char* As = dynsm;                  // 3 * 8192 B
  char* Bs = dynsm + 24576;          // 3 * 32768 B
  float* wsm = (float*)(dynsm + 24576 + 98304);  // 32 KB
  __shared__ float sred[64][16];
  __shared__ float sden[64];
  const int t = threadIdx.x, bm = blockIdx.x;
  const int warp = t>>5, lane = t&31, wm = warp&1, wn = warp>>1, g = lane>>2, tg = lane&3;
  float acc[2][4][4] = {};
  float dpart[2] = {0.f, 0.f};
  for (int i=t; i<2048; i+=512) ((float4*)wsm)[i] = ((const float4*)g_w)[i];
  // B fill: 256 rows x 8 chunks, 4/thread
  const int br = t>>1, bc0 = (t&1)*4;
  const uint32_t bdst = sm_u32(Bs) + br*128;
  const __half* bsrc = g_wht + (size_t)br*N_NODES + bc0*8;
  auto fillB = [&](int s, int kt){
#pragma unroll
    for (int i=0;i<4;i++)
      cp16(bdst + s*32768 + (((bc0+i) ^ (br&7)) << 4), bsrc + kt*64 + i*8);
  };
  // A slots: 64 rows x 16 int4-cols = 1024 slots, 2/thread
  int row_[2], c4_[2], gi_[2];
  const int4* aptr[2];
  uint32_t hdst[2];
#pragma unroll
  for (int i=0;i<2;i++){
    int slot = t + i*512;
    row_[i] = slot >> 4; c4_[i] = slot & 15;
    gi_[i] = bm*64 + row_[i];
    aptr[i] = (const int4*)(adj + (size_t)gi_[i]*N_NODES + c4_[i]*4);
    hdst[i] = sm_u32(As) + (row_[i]*64 + (((c4_[i]>>1) ^ (row_[i]&7)) << 3) + (c4_[i]&1)*4)*2;
  }
  __syncthreads();   // wsm visible before first build
  auto buildA = [&](int s, int c, int4* av){
#pragma unroll
    for (int i=0;i<2;i++){
      int j = c*64 + c4_[i]*4;
      int4 a = av[i];
      int m0 = (a.x!=0) | (gi_[i]==j);
      int m1 = (a.y!=0) | (gi_[i]==j+1);
      int m2 = (a.z!=0) | (gi_[i]==j+2);
      int m3 = (a.w!=0) | (gi_[i]==j+3);
      float4 wv = ((const float4*)wsm)[c*16 + c4_[i]];
      dpart[i] += (m0?wv.x:0.f) + (m1?wv.y:0.f) + (m2?wv.z:0.f) + (m3?wv.w:0.f);
      uint32_t u0 = (m0 ? 0x3C00u : 0u) | (m1 ? 0x3C000000u : 0u);
      uint32_t u1 = (m2 ? 0x3C00u : 0u) | (m3 ? 0x3C000000u : 0u);
      asm volatile("st.shared.v2.b32 [%0], {%1,%2};" :: "r"(hdst[i] + s*8192), "r"(u0), "r"(u1));
    }
  };
  const int KT = N_NODES/64;
  int4 avc[2], avn[2];
  // prologue: stages 0,1
#pragma unroll
  for (int i=0;i<2;i++) avc[i] = aptr[i][0*16];
  buildA(0, 0, avc);
#pragma unroll
  for (int i=0;i<2;i++) avc[i] = aptr[i][1*16];
  buildA(1, 1, avc);
#pragma unroll
  for (int i=0;i<2;i++) avc[i] = aptr[i][2*16];   // for chunk 2 (iter 0)
  fillB(0,0); cpcommit();
  fillB(1,1); cpcommit();
  for (int kt=0; kt<KT; kt++){
    cpwaitg<1>();
    __syncthreads();
    if (kt+2 < KT){
      int s2 = (kt+2)%3;
      buildA(s2, kt+2, avc);
      fillB(s2, kt+2);
      if (kt+3 < KT){
#pragma unroll
        for (int i=0;i<2;i++) avn[i] = aptr[i][(kt+3)*16];
#pragma unroll
        for (int i=0;i<2;i++) avc[i] = avn[i];
      }
    }
    cpcommit();
    int s = kt%3;
    mma_tile(sm_u32(As) + s*8192, sm_u32(Bs) + s*32768, acc, wm, wn, lane);
  }
  // denominator reduction
  __syncthreads();
#pragma unroll
  for (int i=0;i<2;i++) sred[row_[i]][c4_[i]] = dpart[i];
  __syncthreads();
  if (t < 64){
    float s = 0.f;
#pragma unroll
    for (int q=0;q<16;q++) s += sred[t][q];
    sden[t] = s;
  }
  __syncthreads();
#pragma unroll
  for (int mi=0; mi<2; mi++)
#pragma unroll
    for (int ni=0; ni<4; ni++){
      int r = wm*32 + mi*16 + g, c = wn*32 + ni*8 + tg*2;
      float i0 = 1.f/sden[r], i8 = 1.f/sden[r+8];
      size_t go = (size_t)(bm*64+r)*F_OUT + c;
      *(float2*)(out+go)         = make_float2(fmaxf(acc[mi][ni][0]*i0,0.f), fmaxf(acc[mi][ni][1]*i0,0.f));
      *(float2*)(out+go+8*F_OUT) = make_float2(fmaxf(acc[mi][ni][2]*i8,0.f), fmaxf(acc[mi][ni][3]*i8,0.f));
    }
}

extern "C" void kernel_launch(void* const* d_in, const int* in_sizes, int n_in,
                              void* d_out, int out_size){
  const int*   adj  = (const int*)d_in[0];
  const float* x    = (const float*)d_in[1];
  const float* wgt  = (const float*)d_in[2];
  const float* bias = (const float*)d_in[3];
  const float* phi  = (const float*)d_in[4];
  float* out = (float*)d_out;
  cudaFuncSetAttribute(k_gemm1, cudaFuncAttributeMaxDynamicSharedMemorySize, 122880);
  cudaFuncSetAttribute(k_gemm2, cudaFuncAttributeMaxDynamicSharedMemorySize, 155648);
  k_convxw<<<16896, 256>>>(x, wgt);           // 1
  k_ucc<<<65, 256>>>(wgt, bias, phi);         // 2
  k_bvec<<<N_NODES/8, 256>>>(x);              // 3
  k_gemm1<<<128, 512, 122880>>>(bias);        // 4
  k_maxw<<<1, 1024>>>();                      // 5
  k_wht<<<dim3(256,8), 256>>>();              // 6
  k_gemm2<<<128, 512, 155648>>>(adj, out);    // 7
}